// round 14
// baseline (speedup 1.0000x reference)
#include <cuda_runtime.h>
#include <cuda_bf16.h>
#include <cstdint>

#define Hh 126
#define Ww 126
#define WP 128
#define NPIX (Hh*Ww)        // 15876
#define PLANE (Hh*WP)       // 16128
#define NLAYER 6

#define SWZ(b) ((b) ^ (((b) >> 3) & 0x70))

// ping-pong activation buffers + involution weight buffer
__device__ float g_x[64*PLANE];     // ~4.1 MB
__device__ float g_y[64*PLANE];     // ~4.1 MB
__device__ float g_w[196*PLANE];    // ~12.6 MB
// pre-swizzled hi/lo bf16 conv_out weights: per shift s: [128 oc][64 ic],
// 16KB image with SW128 swizzle baked in
__device__ __nv_bfloat16 g_wth[9*8192];
__device__ __nv_bfloat16 g_wtl[9*8192];

__device__ __forceinline__ uint32_t smem_u32(const void* p) {
    uint32_t a;
    asm("{ .reg .u64 t; cvta.to.shared.u64 t, %1; cvt.u32.u64 %0, t; }"
        : "=r"(a) : "l"(p));
    return a;
}
__device__ __forceinline__ void ldm_x4(uint32_t* r, uint32_t addr) {
    asm volatile("ldmatrix.sync.aligned.m8n8.x4.shared.b16 {%0,%1,%2,%3}, [%4];"
        : "=r"(r[0]), "=r"(r[1]), "=r"(r[2]), "=r"(r[3]) : "r"(addr));
}
__device__ __forceinline__ void mma_bf16(float* d, const uint32_t* a, const uint32_t* b) {
    asm volatile(
        "mma.sync.aligned.m16n8k16.row.col.f32.bf16.bf16.f32 "
        "{%0,%1,%2,%3}, {%4,%5,%6,%7}, {%8,%9}, {%0,%1,%2,%3};"
        : "+f"(d[0]), "+f"(d[1]), "+f"(d[2]), "+f"(d[3])
        : "r"(a[0]), "r"(a[1]), "r"(a[2]), "r"(a[3]), "r"(b[0]), "r"(b[1]));
}

// ---------------------------------------------------------------------------
// conv_in: (1,3,128,128) -> (1,64,126,126), 3x3 valid conv
// ---------------------------------------------------------------------------
__global__ __launch_bounds__(256) void k_conv_in(const float* __restrict__ in,
                                                 const float* __restrict__ wt,
                                                 const float* __restrict__ bias,
                                                 float* __restrict__ out)
{
    int t = blockIdx.x * 256 + threadIdx.x;
    int c = blockIdx.y;
    int y = t >> 7, x = t & 127;
    if (y >= Hh || x >= Ww) return;
    float acc = bias[c];
    const float* wc = wt + c * 27;
    #pragma unroll
    for (int i = 0; i < 3; i++)
        #pragma unroll
        for (int r = 0; r < 3; r++)
            #pragma unroll
            for (int s = 0; s < 3; s++)
                acc += wc[(i*3+r)*3+s] * in[(i*128 + (y+r))*128 + (x+s)];
    out[c*PLANE + y*WP + x] = acc;
}

// ---------------------------------------------------------------------------
// kgen v6 (best): 256 threads / 32 pixels, 2 pixels per thread.
// ---------------------------------------------------------------------------
__global__ __launch_bounds__(256) void k_kgen(const float* __restrict__ src,
    const float* __restrict__ wr, const float* __restrict__ br,
    const float* __restrict__ gmm, const float* __restrict__ bet,
    const float* __restrict__ mu, const float* __restrict__ var,
    const float* __restrict__ ws, const float* __restrict__ bs)
{
    __shared__ alignas(16) float xs2[32*68];
    __shared__ alignas(16) float ts[32*20];

    int tid = threadIdx.x;
    int pix0 = blockIdx.x * 32;
    int p = tid & 15;
    int c = tid >> 4;

    for (int i = tid; i < 2048; i += 256) {
        int ic = i >> 5, pp = i & 31;
        int px2 = pix0 + pp;
        float v = 0.f;
        if (px2 < NPIX) {
            int y2 = px2 / 126;
            v = src[ic*PLANE + y2*WP + (px2 - y2*126)];
        }
        xs2[pp*68 + ic] = v;
    }
    __syncthreads();

    {
        float a0 = 0.f, a1 = 0.f;
        const float4* wv4 = (const float4*)(wr + c*64);
        #pragma unroll
        for (int i4 = 0; i4 < 16; i4++) {
            float4 wv = __ldg(&wv4[i4]);
            float4 xa = *(const float4*)&xs2[p*68 + i4*4];
            float4 xb = *(const float4*)&xs2[(p+16)*68 + i4*4];
            a0 += xa.x*wv.x + xa.y*wv.y + xa.z*wv.z + xa.w*wv.w;
            a1 += xb.x*wv.x + xb.y*wv.y + xb.z*wv.z + xb.w*wv.w;
        }
        float s = __ldg(&gmm[c]) * rsqrtf(__ldg(&var[c]) + 1e-5f);
        float h = (__ldg(&br[c]) - __ldg(&mu[c])) * s + __ldg(&bet[c]);
        ts[p*20 + c]      = fmaxf(a0 * s + h, 0.f);
        ts[(p+16)*20 + c] = fmaxf(a1 * s + h, 0.f);
    }
    __syncthreads();

    float tA[16], tB[16];
    #pragma unroll
    for (int k = 0; k < 4; k++) {
        float4 va = *(const float4*)&ts[p*20 + k*4];
        tA[k*4] = va.x; tA[k*4+1] = va.y; tA[k*4+2] = va.z; tA[k*4+3] = va.w;
        float4 vb = *(const float4*)&ts[(p+16)*20 + k*4];
        tB[k*4] = vb.x; tB[k*4+1] = vb.y; tB[k*4+2] = vb.z; tB[k*4+3] = vb.w;
    }
    int pixA = pix0 + p, pixB = pix0 + p + 16;
    bool vA = pixA < NPIX, vB = pixB < NPIX;
    int addrA = 0, addrB = 0;
    if (vA) { int yy = pixA / 126; addrA = yy*WP + (pixA - yy*126); }
    if (vB) { int yy = pixB / 126; addrB = yy*WP + (pixB - yy*126); }

    #pragma unroll 1
    for (int j = c; j < 196; j += 16) {
        const float4* wv4 = (const float4*)(ws + j*16);
        float4 w0 = __ldg(&wv4[0]), w1 = __ldg(&wv4[1]);
        float4 w2 = __ldg(&wv4[2]), w3 = __ldg(&wv4[3]);
        float bj = __ldg(&bs[j]);
        float aA = bj, aB = bj;
        aA += w0.x*tA[0]  + w0.y*tA[1]  + w0.z*tA[2]  + w0.w*tA[3];
        aB += w0.x*tB[0]  + w0.y*tB[1]  + w0.z*tB[2]  + w0.w*tB[3];
        aA += w1.x*tA[4]  + w1.y*tA[5]  + w1.z*tA[6]  + w1.w*tA[7];
        aB += w1.x*tB[4]  + w1.y*tB[5]  + w1.z*tB[6]  + w1.w*tB[7];
        aA += w2.x*tA[8]  + w2.y*tA[9]  + w2.z*tA[10] + w2.w*tA[11];
        aB += w2.x*tB[8]  + w2.y*tB[9]  + w2.z*tB[10] + w2.w*tB[11];
        aA += w3.x*tA[12] + w3.y*tA[13] + w3.z*tA[14] + w3.w*tA[15];
        aB += w3.x*tB[12] + w3.y*tB[13] + w3.z*tB[14] + w3.w*tB[15];
        if (vA) g_w[j*PLANE + addrA] = aA;
        if (vB) g_w[j*PLANE + addrB] = aB;
    }
}

// ---------------------------------------------------------------------------
// agg v5: channel-split for occupancy. 32x16 tile, 4 ch/block (quarter of a
// group), 2 px x 4 ch per thread, 256 threads. grid (4, 8, 16) = 512 blocks.
// smem 14KB. x-halo per channel loaded once (no halo inflation from split);
// per-pixel kernel w read by 4 blocks -> extra L2 traffic only.
// ---------------------------------------------------------------------------
#define AGG_ROWS 22
#define AGG_PCH  40

__global__ __launch_bounds__(256) void k_agg(const float* __restrict__ src,
                                             float* __restrict__ dst)
{
    __shared__ alignas(16) float xs[AGG_ROWS*AGG_PCH*4];

    int g    = blockIdx.z >> 2;
    int quar = blockIdx.z & 3;
    int x0 = blockIdx.x * 32, y0 = blockIdx.y * 16;
    int tid = threadIdx.x;

    // loader: 4 ch x 22 rows x 38 positions
    for (int i = tid; i < 4*22*38; i += 256) {
        int c = i / 836; int rem = i - c*836;
        int r = rem / 38; int pp = rem - r*38;
        int gy = y0 + r - 3, gx = x0 + pp - 3;
        float v = 0.f;
        if ((unsigned)gy < 126u && (unsigned)gx < 126u)
            v = src[(g*16 + quar*4 + c)*PLANE + gy*WP + gx];
        int chunk = r*AGG_PCH + pp;
        int byte = chunk * 16;
        *(float*)((char*)xs + SWZ(byte) + c*4) = v;
    }
    __syncthreads();

    int ty = tid >> 4;            // 0..15
    int xp = (tid & 15) * 2;      // 0,2,...,30
    int gy = y0 + ty;
    if (gy >= 126) return;
    int gx0 = x0 + xp;

    const float* wbase = g_w + (g*49)*PLANE + gy*WP + gx0;

    float acc[4][2];
    #pragma unroll
    for (int cc = 0; cc < 4; cc++) { acc[cc][0] = 0.f; acc[cc][1] = 0.f; }

    #pragma unroll 1
    for (int kh = 0; kh < 7; kh++) {
        float2 wv[7];
        #pragma unroll
        for (int kw = 0; kw < 7; kw++)
            wv[kw] = *(const float2*)(wbase + (kh*7 + kw)*PLANE);

        int rowbase = (ty + kh)*AGG_PCH;
        float4 xq[8];
        #pragma unroll
        for (int j = 0; j < 8; j++) {
            int byte = (rowbase + xp + j) * 16;
            xq[j] = *(const float4*)((const char*)xs + SWZ(byte));
        }
        #pragma unroll
        for (int kw = 0; kw < 7; kw++) {
            #pragma unroll
            for (int q = 0; q < 2; q++) {
                float w = q ? wv[kw].y : wv[kw].x;
                float4 xv = xq[q + kw];
                acc[0][q] += w * xv.x;
                acc[1][q] += w * xv.y;
                acc[2][q] += w * xv.z;
                acc[3][q] += w * xv.w;
            }
        }
    }

    #pragma unroll
    for (int cc = 0; cc < 4; cc++) {
        int ch = g*16 + quar*4 + cc;
        float* o = dst + ch*PLANE + gy*WP + gx0;
        #pragma unroll
        for (int q = 0; q < 2; q++)
            if (gx0 + q < 126) o[q] = fmaxf(acc[cc][q], 0.f);
    }
}

// ---------------------------------------------------------------------------
// wprep: transpose + hi/lo split + SW128-swizzle conv_out weights.
// ---------------------------------------------------------------------------
__global__ __launch_bounds__(256) void k_wprep(const float* __restrict__ cow)
{
    int idx = blockIdx.x * 256 + threadIdx.x;     // 9*128*64 = 73728
    if (idx >= 73728) return;
    int ic = idx & 63;
    int oc = (idx >> 6) & 127;
    int s  = idx >> 13;
    int kh = s / 3, kw = s - kh*3;
    float w = cow[oc*576 + ic*9 + kh*3 + kw];
    __nv_bfloat16 h = __float2bfloat16(w);
    __nv_bfloat16 l = __float2bfloat16(w - __bfloat162float(h));
    int off = SWZ(oc*128 + ic*2) >> 1;            // element offset
    g_wth[s*8192 + off] = h;
    g_wtl[s*8192 + off] = l;
}

// ---------------------------------------------------------------------------
// conv_out_mma: bf16 hi/lo implicit GEMM (ldmatrix + mma.sync.m16n8k16).
// ---------------------------------------------------------------------------
#define CO_SMEM 90112

__global__ __launch_bounds__(256) void k_conv_out_mma(const float* __restrict__ src,
    const float* __restrict__ bias, float* __restrict__ out)
{
    extern __shared__ char dsm[];
    uint32_t base = smem_u32(dsm);
    uint32_t Th = (base + 1023) & ~1023u;
    uint32_t Tl = Th + 27648;                 // 3*72*128 bytes each
    uint32_t Wh = Tl + 27648;
    uint32_t Wl = Wh + 16384;
    char* Th_p = dsm + (Th - base);
    char* Tl_p = dsm + (Tl - base);
    char* Wh_p = dsm + (Wh - base);
    char* Wl_p = dsm + (Wl - base);

    int tid = threadIdx.x;
    int lane = tid & 31, w = tid >> 5;
    int y  = blockIdx.x;                      // output row 0..123
    int x0 = blockIdx.y * 64;
    int pxb = (w & 3) * 16;
    int ocb = (w >> 2) * 64;

    for (int i = tid; i < 3*32*66; i += 256) {
        int col = i % 66;
        int rest = i / 66;
        int icp = rest & 31;
        int v = rest >> 5;
        int gcol = x0 + col;
        float f0 = 0.f, f1 = 0.f;
        if (gcol < WP) {
            const float* pp = src + (2*icp)*PLANE + (y+v)*WP + gcol;
            f0 = __ldg(pp);
            f1 = __ldg(pp + PLANE);
        }
        __nv_bfloat16 h0 = __float2bfloat16(f0);
        __nv_bfloat16 h1 = __float2bfloat16(f1);
        __nv_bfloat16 l0 = __float2bfloat16(f0 - __bfloat162float(h0));
        __nv_bfloat16 l1 = __float2bfloat16(f1 - __bfloat162float(h1));
        uint32_t hu = (uint32_t)__bfloat16_as_ushort(h0)
                    | ((uint32_t)__bfloat16_as_ushort(h1) << 16);
        uint32_t lu = (uint32_t)__bfloat16_as_ushort(l0)
                    | ((uint32_t)__bfloat16_as_ushort(l1) << 16);
        uint32_t off = SWZ((uint32_t)((v*72 + col)*128 + icp*4));
        *(uint32_t*)(Th_p + off) = hu;
        *(uint32_t*)(Tl_p + off) = lu;
    }

    int aRow  = lane & 15;
    int aHalf = (lane >> 4) * 8;
    int bRow  = (lane & 7) + ((lane >> 4) << 3);
    int bHalf = ((lane >> 3) & 1) * 8;

    float acc[8][4];
    #pragma unroll
    for (int j = 0; j < 8; j++)
        #pragma unroll
        for (int q = 0; q < 4; q++) acc[j][q] = 0.f;

    #pragma unroll 1
    for (int s = 0; s < 9; s++) {
        int kh = s / 3, kw = s - kh*3;
        __syncthreads();
        {
            const uint4* sh = (const uint4*)(g_wth + s*8192);
            const uint4* sl = (const uint4*)(g_wtl + s*8192);
            uint4* dh = (uint4*)Wh_p;
            uint4* dl = (uint4*)Wl_p;
            #pragma unroll
            for (int i = 0; i < 4; i++) {
                dh[tid + i*256] = __ldg(&sh[tid + i*256]);
                dl[tid + i*256] = __ldg(&sl[tid + i*256]);
            }
        }
        __syncthreads();

        int cA = pxb + aRow + kw;
        uint32_t arow = (uint32_t)((kh*72 + cA)*128);

        #pragma unroll 1
        for (int pass = 0; pass < 3; pass++) {
            uint32_t Ab = (pass == 2) ? Tl : Th;
            uint32_t Bb = (pass == 1) ? Wl : Wh;
            #pragma unroll
            for (int kk = 0; kk < 4; kk++) {
                uint32_t a[4];
                ldm_x4(a, Ab + SWZ(arow + (uint32_t)((kk*16 + aHalf)*2)));
                #pragma unroll
                for (int j = 0; j < 4; j++) {
                    uint32_t b[4];
                    uint32_t boff = (uint32_t)((ocb + j*16 + bRow)*128
                                              + (kk*16 + bHalf)*2);
                    ldm_x4(b, Bb + SWZ(boff));
                    mma_bf16(acc[2*j],     a, b);
                    mma_bf16(acc[2*j + 1], a, b + 2);
                }
            }
        }
    }

    int r0 = lane >> 2;
    int nc = (lane & 3) * 2;
    int x1 = x0 + pxb + r0;
    int x2 = x1 + 8;
    #pragma unroll
    for (int j = 0; j < 8; j++) {
        int oc = ocb + j*8 + nc;
        float b0 = __ldg(bias + oc), b1 = __ldg(bias + oc + 1);
        if (x1 < 124) {
            out[(oc*124 + y)*124 + x1]       = acc[j][0] + b0;
            out[((oc+1)*124 + y)*124 + x1]   = acc[j][1] + b1;
        }
        if (x2 < 124) {
            out[(oc*124 + y)*124 + x2]       = acc[j][2] + b0;
            out[((oc+1)*124 + y)*124 + x2]   = acc[j][3] + b1;
        }
    }
}

// ---------------------------------------------------------------------------
extern "C" void kernel_launch(void* const* d_in, const int* in_sizes, int n_in,
                              void* d_out, int out_size)
{
    const float* input = (const float*)d_in[0];
    const float* ciw   = (const float*)d_in[1];
    const float* cib   = (const float*)d_in[2];
    const float* wr    = (const float*)d_in[3];
    const float* brr   = (const float*)d_in[4];
    const float* gmm   = (const float*)d_in[5];
    const float* bet   = (const float*)d_in[6];
    const float* mu    = (const float*)d_in[7];
    const float* var   = (const float*)d_in[8];
    const float* ws    = (const float*)d_in[9];
    const float* bs    = (const float*)d_in[10];
    const float* cow   = (const float*)d_in[11];
    const float* cob   = (const float*)d_in[12];

    float *px, *py;
    cudaGetSymbolAddress((void**)&px, g_x);
    cudaGetSymbolAddress((void**)&py, g_y);
    cudaFuncSetAttribute(k_conv_out_mma,
                         cudaFuncAttributeMaxDynamicSharedMemorySize, CO_SMEM);

    k_wprep<<<288, 256>>>(cow);
    k_conv_in<<<dim3(63, 64), 256>>>(input, ciw, cib, px);

    float* cur = px;
    float* nxt = py;
    for (int l = 0; l < NLAYER; l++) {
        k_kgen<<<497, 256>>>(cur, wr + l*1024, brr + l*16, gmm + l*16, bet + l*16,
                             mu + l*16, var + l*16, ws + l*3136, bs + l*196);
        k_agg<<<dim3(4, 8, 16), 256>>>(cur, nxt);
        float* t = cur; cur = nxt; nxt = t;
    }
    k_conv_out_mma<<<dim3(124, 2), 256, CO_SMEM>>>(cur, cob, (float*)d_out);
}

// round 15
// speedup vs baseline: 1.0793x; 1.0793x over previous
#include <cuda_runtime.h>
#include <cuda_bf16.h>
#include <cstdint>

#define Hh 126
#define Ww 126
#define WP 128
#define NPIX (Hh*Ww)        // 15876
#define PLANE (Hh*WP)       // 16128
#define NLAYER 6

#define SWZ(b) ((b) ^ (((b) >> 3) & 0x70))

// ping-pong activation buffers + involution weight buffer
__device__ float g_x[64*PLANE];     // ~4.1 MB
__device__ float g_y[64*PLANE];     // ~4.1 MB
__device__ float g_w[196*PLANE];    // ~12.6 MB
// pre-swizzled hi/lo bf16 conv_out weights: per shift s: [128 oc][64 ic]
__device__ __nv_bfloat16 g_wth[9*8192];
__device__ __nv_bfloat16 g_wtl[9*8192];
// pre-packed hi/lo bf16 span weights per layer: [256 j (pad 196)][16 c],
// 32B rows with XOR-16B layout baked in. 4096 bf16 per layer.
__device__ __nv_bfloat16 g_ksh[NLAYER*4096];
__device__ __nv_bfloat16 g_ksl[NLAYER*4096];

__device__ __forceinline__ uint32_t smem_u32(const void* p) {
    uint32_t a;
    asm("{ .reg .u64 t; cvta.to.shared.u64 t, %1; cvt.u32.u64 %0, t; }"
        : "=r"(a) : "l"(p));
    return a;
}
__device__ __forceinline__ void ldm_x4(uint32_t* r, uint32_t addr) {
    asm volatile("ldmatrix.sync.aligned.m8n8.x4.shared.b16 {%0,%1,%2,%3}, [%4];"
        : "=r"(r[0]), "=r"(r[1]), "=r"(r[2]), "=r"(r[3]) : "r"(addr));
}
__device__ __forceinline__ void mma_bf16(float* d, const uint32_t* a, const uint32_t* b) {
    asm volatile(
        "mma.sync.aligned.m16n8k16.row.col.f32.bf16.bf16.f32 "
        "{%0,%1,%2,%3}, {%4,%5,%6,%7}, {%8,%9}, {%0,%1,%2,%3};"
        : "+f"(d[0]), "+f"(d[1]), "+f"(d[2]), "+f"(d[3])
        : "r"(a[0]), "r"(a[1]), "r"(a[2]), "r"(a[3]), "r"(b[0]), "r"(b[1]));
}

// ---------------------------------------------------------------------------
// conv_in
// ---------------------------------------------------------------------------
__global__ __launch_bounds__(256) void k_conv_in(const float* __restrict__ in,
                                                 const float* __restrict__ wt,
                                                 const float* __restrict__ bias,
                                                 float* __restrict__ out)
{
    int t = blockIdx.x * 256 + threadIdx.x;
    int c = blockIdx.y;
    int y = t >> 7, x = t & 127;
    if (y >= Hh || x >= Ww) return;
    float acc = bias[c];
    const float* wc = wt + c * 27;
    #pragma unroll
    for (int i = 0; i < 3; i++)
        #pragma unroll
        for (int r = 0; r < 3; r++)
            #pragma unroll
            for (int s = 0; s < 3; s++)
                acc += wc[(i*3+r)*3+s] * in[(i*128 + (y+r))*128 + (x+s)];
    out[c*PLANE + y*WP + x] = acc;
}

// ---------------------------------------------------------------------------
// wprep2: pack span weights Ws (per layer) to hi/lo bf16 [256 j][16 c],
// 32B rows with XOR-16B layout baked in.
// ---------------------------------------------------------------------------
__global__ __launch_bounds__(256) void k_wprep2(const float* __restrict__ ws)
{
    int idx = blockIdx.x * 256 + threadIdx.x;   // 6*256*16 = 24576
    if (idx >= NLAYER*4096) return;
    int k = idx & 15;
    int j = (idx >> 4) & 255;
    int l = idx >> 12;
    float v = (j < 196) ? ws[l*3136 + j*16 + k] : 0.f;
    __nv_bfloat16 h = __float2bfloat16(v);
    __nv_bfloat16 lo = __float2bfloat16(v - __bfloat162float(h));
    int byte = j*32 + (((k >> 3) ^ ((j >> 2) & 1)) << 4) + (k & 7)*2;
    g_ksh[l*4096 + (byte >> 1)] = h;
    g_ksl[l*4096 + (byte >> 1)] = lo;
}

// ---------------------------------------------------------------------------
// kgen v8: Phase A scalar (v6), Phase B via mma.sync bf16 hi/lo.
// 256 threads / 32 pixels. grid 497.
// ---------------------------------------------------------------------------
__global__ __launch_bounds__(256) void k_kgen(const float* __restrict__ src,
    const float* __restrict__ wr, const float* __restrict__ br,
    const float* __restrict__ gmm, const float* __restrict__ bet,
    const float* __restrict__ mu, const float* __restrict__ var,
    const __nv_bfloat16* __restrict__ ksh, const __nv_bfloat16* __restrict__ ksl,
    const float* __restrict__ bs)
{
    __shared__ alignas(16) float xs2[32*68];
    __shared__ alignas(16) float ts[32*20];
    __shared__ alignas(16) __nv_bfloat16 tAh[32*16];   // [px][c] 32B rows
    __shared__ alignas(16) __nv_bfloat16 tAl[32*16];
    __shared__ alignas(16) __nv_bfloat16 Bh[4096];     // [256 j][16 c]
    __shared__ alignas(16) __nv_bfloat16 Bl[4096];
    __shared__ float bs_s[200];
    __shared__ int saddr[32];

    int tid = threadIdx.x;
    int pix0 = blockIdx.x * 32;
    int p = tid & 15;
    int c = tid >> 4;

    // stage x + B weights + bias + addr table (all independent)
    for (int i = tid; i < 2048; i += 256) {
        int ic = i >> 5, pp = i & 31;
        int px2 = pix0 + pp;
        float v = 0.f;
        if (px2 < NPIX) {
            int y2 = px2 / 126;
            v = src[ic*PLANE + y2*WP + (px2 - y2*126)];
        }
        xs2[pp*68 + ic] = v;
    }
    {
        const uint4* sh = (const uint4*)ksh;
        const uint4* sl = (const uint4*)ksl;
        ((uint4*)Bh)[tid]       = __ldg(&sh[tid]);
        ((uint4*)Bh)[tid + 256] = __ldg(&sh[tid + 256]);
        ((uint4*)Bl)[tid]       = __ldg(&sl[tid]);
        ((uint4*)Bl)[tid + 256] = __ldg(&sl[tid + 256]);
    }
    if (tid < 200) bs_s[tid] = (tid < 196) ? __ldg(bs + tid) : 0.f;
    if (tid < 32) {
        int pix = pix0 + tid;
        if (pix < NPIX) {
            int yy = pix / 126;
            saddr[tid] = yy*WP + (pix - yy*126);
        } else saddr[tid] = -1;
    }
    __syncthreads();

    // Phase A: t(c, p) and t(c, p+16)   (scalar, v6)
    {
        float a0 = 0.f, a1 = 0.f;
        const float4* wv4 = (const float4*)(wr + c*64);
        #pragma unroll
        for (int i4 = 0; i4 < 16; i4++) {
            float4 wv = __ldg(&wv4[i4]);
            float4 xa = *(const float4*)&xs2[p*68 + i4*4];
            float4 xb = *(const float4*)&xs2[(p+16)*68 + i4*4];
            a0 += xa.x*wv.x + xa.y*wv.y + xa.z*wv.z + xa.w*wv.w;
            a1 += xb.x*wv.x + xb.y*wv.y + xb.z*wv.z + xb.w*wv.w;
        }
        float s = __ldg(&gmm[c]) * rsqrtf(__ldg(&var[c]) + 1e-5f);
        float h = (__ldg(&br[c]) - __ldg(&mu[c])) * s + __ldg(&bet[c]);
        ts[p*20 + c]      = fmaxf(a0 * s + h, 0.f);
        ts[(p+16)*20 + c] = fmaxf(a1 * s + h, 0.f);
    }
    __syncthreads();

    // pack t -> hi/lo bf16 A-operand [px][16 c], 32B rows, XOR-16B
    {
        int px = tid >> 3, cp = tid & 7;
        float t0 = ts[px*20 + 2*cp], t1 = ts[px*20 + 2*cp + 1];
        __nv_bfloat16 h0 = __float2bfloat16(t0), h1 = __float2bfloat16(t1);
        __nv_bfloat16 l0 = __float2bfloat16(t0 - __bfloat162float(h0));
        __nv_bfloat16 l1 = __float2bfloat16(t1 - __bfloat162float(h1));
        uint32_t hu = (uint32_t)__bfloat16_as_ushort(h0)
                    | ((uint32_t)__bfloat16_as_ushort(h1) << 16);
        uint32_t lu = (uint32_t)__bfloat16_as_ushort(l0)
                    | ((uint32_t)__bfloat16_as_ushort(l1) << 16);
        uint32_t off = (uint32_t)(px*32 + (((cp >> 2) ^ ((px >> 2) & 1)) << 4)
                                 + (cp & 3)*4);
        *(uint32_t*)((char*)tAh + off) = hu;
        *(uint32_t*)((char*)tAl + off) = lu;
    }
    __syncthreads();

    // Phase B: D[32 px][256 j] = t @ Ws^T, hi/lo 3-pass.
    // warp w: m-tile = w&1 (16 px), j-group q = w>>2... (w>>1)*64 j range.
    int lane = tid & 31, w = tid >> 5;
    int mw = w & 1, q = w >> 1;

    uint32_t Ah_b = smem_u32(tAh), Al_b = smem_u32(tAl);
    uint32_t Bh_b = smem_u32(Bh),  Bl_b = smem_u32(Bl);

    int apx = mw*16 + (lane & 15);
    int ahf = lane >> 4;
    uint32_t aoff = (uint32_t)(apx*32 + ((ahf ^ ((apx >> 2) & 1)) << 4));
    uint32_t ahr[4], alr[4];
    ldm_x4(ahr, Ah_b + aoff);
    ldm_x4(alr, Al_b + aoff);

    float acc[8][4];
    #pragma unroll
    for (int nt = 0; nt < 8; nt++)
        #pragma unroll
        for (int qq = 0; qq < 4; qq++) acc[nt][qq] = 0.f;

    int jr = (lane & 7) + ((lane >> 4) << 3);
    int bhf = (lane >> 3) & 1;
    #pragma unroll
    for (int pr = 0; pr < 4; pr++) {
        int jrow = q*64 + pr*16 + jr;
        uint32_t boff = (uint32_t)(jrow*32 + ((bhf ^ ((jrow >> 2) & 1)) << 4));
        uint32_t bh[4], bl[4];
        ldm_x4(bh, Bh_b + boff);
        ldm_x4(bl, Bl_b + boff);
        mma_bf16(acc[2*pr],     ahr, bh);
        mma_bf16(acc[2*pr + 1], ahr, bh + 2);
        mma_bf16(acc[2*pr],     ahr, bl);
        mma_bf16(acc[2*pr + 1], ahr, bl + 2);
        mma_bf16(acc[2*pr],     alr, bh);
        mma_bf16(acc[2*pr + 1], alr, bh + 2);
    }

    // store: lane holds (px gr / gr+8, j jc/jc+1) per n-tile
    int gr = lane >> 2, jc = (lane & 3)*2;
    int a1 = saddr[mw*16 + gr];
    int a2 = saddr[mw*16 + gr + 8];
    #pragma unroll
    for (int nt = 0; nt < 8; nt++) {
        int j0 = q*64 + nt*8 + jc;
        if (j0 < 196) {
            float b0 = bs_s[j0];
            if (a1 >= 0) g_w[j0*PLANE + a1] = acc[nt][0] + b0;
            if (a2 >= 0) g_w[j0*PLANE + a2] = acc[nt][2] + b0;
        }
        if (j0 + 1 < 196) {
            float b1 = bs_s[j0 + 1];
            if (a1 >= 0) g_w[(j0+1)*PLANE + a1] = acc[nt][1] + b1;
            if (a2 >= 0) g_w[(j0+1)*PLANE + a2] = acc[nt][3] + b1;
        }
    }
}

// ---------------------------------------------------------------------------
// agg (R13 best config): 256 threads, 32x16 tile, 8 ch/block,
// 2 px x 8 ch per thread. grid (4, 8, 8).
// ---------------------------------------------------------------------------
#define AGG_ROWS 22
#define AGG_PCH  40
#define AGG_CHUNKS (AGG_ROWS*2*AGG_PCH)

__global__ __launch_bounds__(256) void k_agg(const float* __restrict__ src,
                                             float* __restrict__ dst)
{
    __shared__ alignas(16) float xs[AGG_CHUNKS*4];

    int g    = blockIdx.z >> 1;
    int half = blockIdx.z & 1;
    int x0 = blockIdx.x * 32, y0 = blockIdx.y * 16;
    int tid = threadIdx.x;

    for (int i = tid; i < 8*22*38; i += 256) {
        int c = i / 836; int rem = i - c*836;
        int r = rem / 38; int pp = rem - r*38;
        int gy = y0 + r - 3, gx = x0 + pp - 3;
        float v = 0.f;
        if ((unsigned)gy < 126u && (unsigned)gx < 126u)
            v = src[(g*16 + half*8 + c)*PLANE + gy*WP + gx];
        int chunk = (r*2 + (c >> 2))*AGG_PCH + pp;
        int byte = chunk * 16;
        *(float*)((char*)xs + SWZ(byte) + (c & 3)*4) = v;
    }
    __syncthreads();

    int ty = tid >> 4;
    int xp = (tid & 15) * 2;
    int gy = y0 + ty;
    if (gy >= 126) return;
    int gx0 = x0 + xp;

    const float* wbase = g_w + (g*49)*PLANE + gy*WP + gx0;

    float acc[8][2];
    #pragma unroll
    for (int cc = 0; cc < 8; cc++) { acc[cc][0] = 0.f; acc[cc][1] = 0.f; }

    #pragma unroll 1
    for (int kh = 0; kh < 7; kh++) {
        float2 wv[7];
        #pragma unroll
        for (int kw = 0; kw < 7; kw++)
            wv[kw] = *(const float2*)(wbase + (kh*7 + kw)*PLANE);

        #pragma unroll
        for (int cg = 0; cg < 2; cg++) {
            int rowbase = ((ty + kh)*2 + cg)*AGG_PCH;
            float4 xq[8];
            #pragma unroll
            for (int j = 0; j < 8; j++) {
                int byte = (rowbase + xp + j) * 16;
                xq[j] = *(const float4*)((const char*)xs + SWZ(byte));
            }
            #pragma unroll
            for (int kw = 0; kw < 7; kw++) {
                #pragma unroll
                for (int q = 0; q < 2; q++) {
                    float w = q ? wv[kw].y : wv[kw].x;
                    float4 xv = xq[q + kw];
                    acc[cg*4+0][q] += w * xv.x;
                    acc[cg*4+1][q] += w * xv.y;
                    acc[cg*4+2][q] += w * xv.z;
                    acc[cg*4+3][q] += w * xv.w;
                }
            }
        }
    }

    #pragma unroll
    for (int cc = 0; cc < 8; cc++) {
        int ch = g*16 + half*8 + cc;
        float* o = dst + ch*PLANE + gy*WP + gx0;
        #pragma unroll
        for (int q = 0; q < 2; q++)
            if (gx0 + q < 126) o[q] = fmaxf(acc[cc][q], 0.f);
    }
}

// ---------------------------------------------------------------------------
// wprep: conv_out weights -> hi/lo bf16 SW128 images
// ---------------------------------------------------------------------------
__global__ __launch_bounds__(256) void k_wprep(const float* __restrict__ cow)
{
    int idx = blockIdx.x * 256 + threadIdx.x;     // 9*128*64 = 73728
    if (idx >= 73728) return;
    int ic = idx & 63;
    int oc = (idx >> 6) & 127;
    int s  = idx >> 13;
    int kh = s / 3, kw = s - kh*3;
    float w = cow[oc*576 + ic*9 + kh*3 + kw];
    __nv_bfloat16 h = __float2bfloat16(w);
    __nv_bfloat16 l = __float2bfloat16(w - __bfloat162float(h));
    int off = SWZ(oc*128 + ic*2) >> 1;
    g_wth[s*8192 + off] = h;
    g_wtl[s*8192 + off] = l;
}

// ---------------------------------------------------------------------------
// conv_out_mma (R13 proven): bf16 hi/lo implicit GEMM via ldmatrix+mma.sync
// ---------------------------------------------------------------------------
#define CO_SMEM 90112

__global__ __launch_bounds__(256) void k_conv_out_mma(const float* __restrict__ src,
    const float* __restrict__ bias, float* __restrict__ out)
{
    extern __shared__ char dsm[];
    uint32_t base = smem_u32(dsm);
    uint32_t Th = (base + 1023) & ~1023u;
    uint32_t Tl = Th + 27648;
    uint32_t Wh = Tl + 27648;
    uint32_t Wl = Wh + 16384;
    char* Th_p = dsm + (Th - base);
    char* Tl_p = dsm + (Tl - base);
    char* Wh_p = dsm + (Wh - base);
    char* Wl_p = dsm + (Wl - base);

    int tid = threadIdx.x;
    int lane = tid & 31, w = tid >> 5;
    int y  = blockIdx.x;
    int x0 = blockIdx.y * 64;
    int pxb = (w & 3) * 16;
    int ocb = (w >> 2) * 64;

    for (int i = tid; i < 3*32*66; i += 256) {
        int col = i % 66;
        int rest = i / 66;
        int icp = rest & 31;
        int v = rest >> 5;
        int gcol = x0 + col;
        float f0 = 0.f, f1 = 0.f;
        if (gcol < WP) {
            const float* pp = src + (2*icp)*PLANE + (y+v)*WP + gcol;
            f0 = __ldg(pp);
            f1 = __ldg(pp + PLANE);
        }
        __nv_bfloat16 h0 = __float2bfloat16(f0);
        __nv_bfloat16 h1 = __float2bfloat16(f1);
        __nv_bfloat16 l0 = __float2bfloat16(f0 - __bfloat162float(h0));
        __nv_bfloat16 l1 = __float2bfloat16(f1 - __bfloat162float(h1));
        uint32_t hu = (uint32_t)__bfloat16_as_ushort(h0)
                    | ((uint32_t)__bfloat16_as_ushort(h1) << 16);
        uint32_t lu = (uint32_t)__bfloat16_as_ushort(l0)
                    | ((uint32_t)__bfloat16_as_ushort(l1) << 16);
        uint32_t off = SWZ((uint32_t)((v*72 + col)*128 + icp*4));
        *(uint32_t*)(Th_p + off) = hu;
        *(uint32_t*)(Tl_p + off) = lu;
    }

    int aRow  = lane & 15;
    int aHalf = (lane >> 4) * 8;
    int bRow  = (lane & 7) + ((lane >> 4) << 3);
    int bHalf = ((lane >> 3) & 1) * 8;

    float acc[8][4];
    #pragma unroll
    for (int j = 0; j < 8; j++)
        #pragma unroll
        for (int q = 0; q < 4; q++) acc[j][q] = 0.f;

    #pragma unroll 1
    for (int s = 0; s < 9; s++) {
        int kh = s / 3, kw = s - kh*3;
        __syncthreads();
        {
            const uint4* sh = (const uint4*)(g_wth + s*8192);
            const uint4* sl = (const uint4*)(g_wtl + s*8192);
            uint4* dh = (uint4*)Wh_p;
            uint4* dl = (uint4*)Wl_p;
            #pragma unroll
            for (int i = 0; i < 4; i++) {
                dh[tid + i*256] = __ldg(&sh[tid + i*256]);
                dl[tid + i*256] = __ldg(&sl[tid + i*256]);
            }
        }
        __syncthreads();

        int cA = pxb + aRow + kw;
        uint32_t arow = (uint32_t)((kh*72 + cA)*128);

        #pragma unroll 1
        for (int pass = 0; pass < 3; pass++) {
            uint32_t Ab = (pass == 2) ? Tl : Th;
            uint32_t Bb = (pass == 1) ? Wl : Wh;
            #pragma unroll
            for (int kk = 0; kk < 4; kk++) {
                uint32_t a[4];
                ldm_x4(a, Ab + SWZ(arow + (uint32_t)((kk*16 + aHalf)*2)));
                #pragma unroll
                for (int j = 0; j < 4; j++) {
                    uint32_t b[4];
                    uint32_t boff = (uint32_t)((ocb + j*16 + bRow)*128
                                              + (kk*16 + bHalf)*2);
                    ldm_x4(b, Bb + SWZ(boff));
                    mma_bf16(acc[2*j],     a, b);
                    mma_bf16(acc[2*j + 1], a, b + 2);
                }
            }
        }
    }

    int r0 = lane >> 2;
    int nc = (lane & 3) * 2;
    int x1 = x0 + pxb + r0;
    int x2 = x1 + 8;
    #pragma unroll
    for (int j = 0; j < 8; j++) {
        int oc = ocb + j*8 + nc;
        float b0 = __ldg(bias + oc), b1 = __ldg(bias + oc + 1);
        if (x1 < 124) {
            out[(oc*124 + y)*124 + x1]       = acc[j][0] + b0;
            out[((oc+1)*124 + y)*124 + x1]   = acc[j][1] + b1;
        }
        if (x2 < 124) {
            out[(oc*124 + y)*124 + x2]       = acc[j][2] + b0;
            out[((oc+1)*124 + y)*124 + x2]   = acc[j][3] + b1;
        }
    }
}

// ---------------------------------------------------------------------------
extern "C" void kernel_launch(void* const* d_in, const int* in_sizes, int n_in,
                              void* d_out, int out_size)
{
    const float* input = (const float*)d_in[0];
    const float* ciw   = (const float*)d_in[1];
    const float* cib   = (const float*)d_in[2];
    const float* wr    = (const float*)d_in[3];
    const float* brr   = (const float*)d_in[4];
    const float* gmm   = (const float*)d_in[5];
    const float* bet   = (const float*)d_in[6];
    const float* mu    = (const float*)d_in[7];
    const float* var   = (const float*)d_in[8];
    const float* ws    = (const float*)d_in[9];
    const float* bs    = (const float*)d_in[10];
    const float* cow   = (const float*)d_in[11];
    const float* cob   = (const float*)d_in[12];

    float *px, *py;
    __nv_bfloat16 *ksh, *ksl;
    cudaGetSymbolAddress((void**)&px, g_x);
    cudaGetSymbolAddress((void**)&py, g_y);
    cudaGetSymbolAddress((void**)&ksh, g_ksh);
    cudaGetSymbolAddress((void**)&ksl, g_ksl);
    cudaFuncSetAttribute(k_conv_out_mma,
                         cudaFuncAttributeMaxDynamicSharedMemorySize, CO_SMEM);

    k_wprep<<<288, 256>>>(cow);
    k_wprep2<<<96, 256>>>(ws);
    k_conv_in<<<dim3(63, 64), 256>>>(input, ciw, cib, px);

    float* cur = px;
    float* nxt = py;
    for (int l = 0; l < NLAYER; l++) {
        k_kgen<<<497, 256>>>(cur, wr + l*1024, brr + l*16, gmm + l*16, bet + l*16,
                             mu + l*16, var + l*16,
                             ksh + l*4096, ksl + l*4096, bs + l*196);
        k_agg<<<dim3(4, 8, 8), 256>>>(cur, nxt);
        float* t = cur; cur = nxt; nxt = t;
    }
    k_conv_out_mma<<<dim3(124, 2), 256, CO_SMEM>>>(cur, cob, (float*)d_out);
}

// round 17
// speedup vs baseline: 1.1784x; 1.0918x over previous
#include <cuda_runtime.h>
#include <cuda_bf16.h>
#include <cstdint>

#define Hh 126
#define Ww 126
#define WP 128
#define NPIX (Hh*Ww)        // 15876
#define PLANE (Hh*WP)       // 16128
#define NLAYER 6

#define SWZ(b) ((b) ^ (((b) >> 3) & 0x70))

// ping-pong activation buffers + involution weight buffer
__device__ float g_x[64*PLANE];     // ~4.1 MB
__device__ float g_y[64*PLANE];     // ~4.1 MB
__device__ float g_w[196*PLANE];    // ~12.6 MB
// pre-swizzled hi/lo bf16 conv_out weights
__device__ __nv_bfloat16 g_wth[9*8192];
__device__ __nv_bfloat16 g_wtl[9*8192];
// pre-packed hi/lo bf16 span weights per layer: [256 j][16 c], XOR-16B rows
__device__ __nv_bfloat16 g_ksh[NLAYER*4096];
__device__ __nv_bfloat16 g_ksl[NLAYER*4096];
// pre-packed hi/lo bf16 reduce weights per layer: [16 c][64 ic], SWZ 128B rows
__device__ __nv_bfloat16 g_krh[NLAYER*1024];
__device__ __nv_bfloat16 g_krl[NLAYER*1024];

__device__ __forceinline__ uint32_t smem_u32(const void* p) {
    uint32_t a;
    asm("{ .reg .u64 t; cvta.to.shared.u64 t, %1; cvt.u32.u64 %0, t; }"
        : "=r"(a) : "l"(p));
    return a;
}
__device__ __forceinline__ void ldm_x4(uint32_t* r, uint32_t addr) {
    asm volatile("ldmatrix.sync.aligned.m8n8.x4.shared.b16 {%0,%1,%2,%3}, [%4];"
        : "=r"(r[0]), "=r"(r[1]), "=r"(r[2]), "=r"(r[3]) : "r"(addr));
}
__device__ __forceinline__ void mma_bf16(float* d, const uint32_t* a, const uint32_t* b) {
    asm volatile(
        "mma.sync.aligned.m16n8k16.row.col.f32.bf16.bf16.f32 "
        "{%0,%1,%2,%3}, {%4,%5,%6,%7}, {%8,%9}, {%0,%1,%2,%3};"
        : "+f"(d[0]), "+f"(d[1]), "+f"(d[2]), "+f"(d[3])
        : "r"(a[0]), "r"(a[1]), "r"(a[2]), "r"(a[3]), "r"(b[0]), "r"(b[1]));
}

// ---------------------------------------------------------------------------
// conv_in
// ---------------------------------------------------------------------------
__global__ __launch_bounds__(256) void k_conv_in(const float* __restrict__ in,
                                                 const float* __restrict__ wt,
                                                 const float* __restrict__ bias,
                                                 float* __restrict__ out)
{
    int t = blockIdx.x * 256 + threadIdx.x;
    int c = blockIdx.y;
    int y = t >> 7, x = t & 127;
    if (y >= Hh || x >= Ww) return;
    float acc = bias[c];
    const float* wc = wt + c * 27;
    #pragma unroll
    for (int i = 0; i < 3; i++)
        #pragma unroll
        for (int r = 0; r < 3; r++)
            #pragma unroll
            for (int s = 0; s < 3; s++)
                acc += wc[(i*3+r)*3+s] * in[(i*128 + (y+r))*128 + (x+s)];
    out[c*PLANE + y*WP + x] = acc;
}

// ---------------------------------------------------------------------------
// wprep2: span weights -> hi/lo bf16 [256 j][16 c], XOR-16B rows
// ---------------------------------------------------------------------------
__global__ __launch_bounds__(256) void k_wprep2(const float* __restrict__ ws)
{
    int idx = blockIdx.x * 256 + threadIdx.x;   // NLAYER*4096
    if (idx >= NLAYER*4096) return;
    int k = idx & 15;
    int j = (idx >> 4) & 255;
    int l = idx >> 12;
    float v = (j < 196) ? ws[l*3136 + j*16 + k] : 0.f;
    __nv_bfloat16 h = __float2bfloat16(v);
    __nv_bfloat16 lo = __float2bfloat16(v - __bfloat162float(h));
    int byte = j*32 + (((k >> 3) ^ ((j >> 2) & 1)) << 4) + (k & 7)*2;
    g_ksh[l*4096 + (byte >> 1)] = h;
    g_ksl[l*4096 + (byte >> 1)] = lo;
}

// ---------------------------------------------------------------------------
// wprep3: reduce weights -> hi/lo bf16 [16 c][64 ic], SWZ 128B rows
// ---------------------------------------------------------------------------
__global__ __launch_bounds__(256) void k_wprep3(const float* __restrict__ wr)
{
    int idx = blockIdx.x * 256 + threadIdx.x;   // NLAYER*1024
    if (idx >= NLAYER*1024) return;
    int ic = idx & 63;
    int c = (idx >> 6) & 15;
    int l = idx >> 10;
    float v = wr[l*1024 + c*64 + ic];
    __nv_bfloat16 h = __float2bfloat16(v);
    __nv_bfloat16 lo = __float2bfloat16(v - __bfloat162float(h));
    int byte = SWZ(c*128 + ic*2);
    g_krh[l*1024 + (byte >> 1)] = h;
    g_krl[l*1024 + (byte >> 1)] = lo;
}

// ---------------------------------------------------------------------------
// kgen v9: BOTH phases via mma.sync bf16 hi/lo. 256 threads / 32 pixels.
// Phase A: t[16c x 32px] = Wr @ x  (warps 0-1)
// Phase B: w[196j x 32px] = Ws @ t (all 8 warps)
// ---------------------------------------------------------------------------
__global__ __launch_bounds__(256) void k_kgen(const float* __restrict__ src,
    const __nv_bfloat16* __restrict__ krh, const __nv_bfloat16* __restrict__ krl,
    const float* __restrict__ br,
    const float* __restrict__ gmm, const float* __restrict__ bet,
    const float* __restrict__ mu, const float* __restrict__ var,
    const __nv_bfloat16* __restrict__ ksh, const __nv_bfloat16* __restrict__ ksl,
    const float* __restrict__ bs)
{
    __shared__ alignas(16) __nv_bfloat16 xBh[2048];    // x [32px][64ic] SWZ
    __shared__ alignas(16) __nv_bfloat16 xBl[2048];
    __shared__ alignas(16) __nv_bfloat16 Arh[1024];    // Wr [16c][64ic] SWZ
    __shared__ alignas(16) __nv_bfloat16 Arl[1024];
    __shared__ alignas(16) __nv_bfloat16 tAh[512];     // t [32px][16c] XOR-16B
    __shared__ alignas(16) __nv_bfloat16 tAl[512];
    __shared__ alignas(16) __nv_bfloat16 Bh[4096];     // Ws [256j][16c]
    __shared__ alignas(16) __nv_bfloat16 Bl[4096];
    __shared__ float bs_s[200];
    __shared__ float scs[16], shs[16];
    __shared__ int saddr[32];

    int tid = threadIdx.x;
    int pix0 = blockIdx.x * 32;
    int lane = tid & 31, w = tid >> 5;

    // ---- stage x as hi/lo bf16 B-operand ----
    for (int i = tid; i < 1024; i += 256) {
        int icp = i >> 5, px = i & 31;
        int pix = pix0 + px;
        float f0 = 0.f, f1 = 0.f;
        if (pix < NPIX) {
            int yy = pix / 126;
            const float* pp = src + (2*icp)*PLANE + yy*WP + (pix - yy*126);
            f0 = __ldg(pp);
            f1 = __ldg(pp + PLANE);
        }
        __nv_bfloat16 h0 = __float2bfloat16(f0), h1 = __float2bfloat16(f1);
        __nv_bfloat16 l0 = __float2bfloat16(f0 - __bfloat162float(h0));
        __nv_bfloat16 l1 = __float2bfloat16(f1 - __bfloat162float(h1));
        uint32_t hu = (uint32_t)__bfloat16_as_ushort(h0)
                    | ((uint32_t)__bfloat16_as_ushort(h1) << 16);
        uint32_t lu = (uint32_t)__bfloat16_as_ushort(l0)
                    | ((uint32_t)__bfloat16_as_ushort(l1) << 16);
        uint32_t off = SWZ((uint32_t)(px*128 + icp*4));
        *(uint32_t*)((char*)xBh + off) = hu;
        *(uint32_t*)((char*)xBl + off) = lu;
    }
    // ---- stage Wr, Ws, bias, BN consts, addr table ----
    if (tid < 128) {
        ((uint4*)Arh)[tid] = __ldg(&((const uint4*)krh)[tid]);
        ((uint4*)Arl)[tid] = __ldg(&((const uint4*)krl)[tid]);
    }
    {
        const uint4* sh = (const uint4*)ksh;
        const uint4* sl = (const uint4*)ksl;
        ((uint4*)Bh)[tid]       = __ldg(&sh[tid]);
        ((uint4*)Bh)[tid + 256] = __ldg(&sh[tid + 256]);
        ((uint4*)Bl)[tid]       = __ldg(&sl[tid]);
        ((uint4*)Bl)[tid + 256] = __ldg(&sl[tid + 256]);
    }
    if (tid < 200) bs_s[tid] = (tid < 196) ? __ldg(bs + tid) : 0.f;
    if (tid < 16) {
        float s = __ldg(&gmm[tid]) * rsqrtf(__ldg(&var[tid]) + 1e-5f);
        scs[tid] = s;
        shs[tid] = (__ldg(&br[tid]) - __ldg(&mu[tid])) * s + __ldg(&bet[tid]);
    }
    if (tid < 32) {
        int pix = pix0 + tid;
        if (pix < NPIX) {
            int yy = pix / 126;
            saddr[tid] = yy*WP + (pix - yy*126);
        } else saddr[tid] = -1;
    }
    __syncthreads();

    // ---- Phase A: warps 0-1 compute t = Wr @ x, BN+ReLU, pack to tA ----
    if (w < 2) {
        uint32_t Ah_b = smem_u32(Arh), Al_b = smem_u32(Arl);
        uint32_t Xh_b = smem_u32(xBh), Xl_b = smem_u32(xBl);
        int aRow  = lane & 15;                  // c row
        int aHalf = (lane >> 4) * 8;            // k half-offset
        int bRow  = (lane & 7) + ((lane >> 4) << 3);
        int bHalf = ((lane >> 3) & 1) * 8;

        float acc[2][4];
        #pragma unroll
        for (int nt = 0; nt < 2; nt++)
            #pragma unroll
            for (int q = 0; q < 4; q++) acc[nt][q] = 0.f;

        int pxr = w*16 + bRow;
        #pragma unroll
        for (int kk = 0; kk < 4; kk++) {
            uint32_t ak = (uint32_t)((kk*16 + aHalf)*2);
            uint32_t bk = (uint32_t)((kk*16 + bHalf)*2);
            uint32_t ah[4], al[4], bh[4], bl[4];
            ldm_x4(ah, Ah_b + SWZ((uint32_t)(aRow*128) + ak));
            ldm_x4(al, Al_b + SWZ((uint32_t)(aRow*128) + ak));
            ldm_x4(bh, Xh_b + SWZ((uint32_t)(pxr*128) + bk));
            ldm_x4(bl, Xl_b + SWZ((uint32_t)(pxr*128) + bk));
            mma_bf16(acc[0], ah, bh);
            mma_bf16(acc[1], ah, bh + 2);
            mma_bf16(acc[0], ah, bl);
            mma_bf16(acc[1], ah, bl + 2);
            mma_bf16(acc[0], al, bh);
            mma_bf16(acc[1], al, bh + 2);
        }

        // unpack D: rows c = lane>>2, +8; cols px = w*16 + nt*8 + (lane&3)*2, +1
        int c0 = lane >> 2;
        int pxc = (lane & 3) * 2;
        #pragma unroll
        for (int nt = 0; nt < 2; nt++) {
            #pragma unroll
            for (int q = 0; q < 4; q++) {
                int c = c0 + (q >> 1)*8;
                int px = w*16 + nt*8 + pxc + (q & 1);
                float t = fmaxf(acc[nt][q] * scs[c] + shs[c], 0.f);
                __nv_bfloat16 h = __float2bfloat16(t);
                __nv_bfloat16 lo = __float2bfloat16(t - __bfloat162float(h));
                uint32_t byte = (uint32_t)(px*32
                               + (((c >> 3) ^ ((px >> 2) & 1)) << 4) + (c & 7)*2);
                *(__nv_bfloat16*)((char*)tAh + byte) = h;
                *(__nv_bfloat16*)((char*)tAl + byte) = lo;
            }
        }
    }
    __syncthreads();

    // ---- Phase B: D[32 px][256 j] = t @ Ws^T, hi/lo 3-pass ----
    int mw = w & 1, q = w >> 1;

    uint32_t Ah_b = smem_u32(tAh), Al_b = smem_u32(tAl);
    uint32_t Bh_b = smem_u32(Bh),  Bl_b = smem_u32(Bl);

    int apx = mw*16 + (lane & 15);
    int ahf = lane >> 4;
    uint32_t aoff = (uint32_t)(apx*32 + ((ahf ^ ((apx >> 2) & 1)) << 4));
    uint32_t ahr[4], alr[4];
    ldm_x4(ahr, Ah_b + aoff);
    ldm_x4(alr, Al_b + aoff);

    float acc[8][4];
    #pragma unroll
    for (int nt = 0; nt < 8; nt++)
        #pragma unroll
        for (int qq = 0; qq < 4; qq++) acc[nt][qq] = 0.f;

    int jr = (lane & 7) + ((lane >> 4) << 3);
    int bhf = (lane >> 3) & 1;
    #pragma unroll
    for (int pr = 0; pr < 4; pr++) {
        int jrow = q*64 + pr*16 + jr;
        uint32_t boff = (uint32_t)(jrow*32 + ((bhf ^ ((jrow >> 2) & 1)) << 4));
        uint32_t bh[4], bl[4];
        ldm_x4(bh, Bh_b + boff);
        ldm_x4(bl, Bl_b + boff);
        mma_bf16(acc[2*pr],     ahr, bh);
        mma_bf16(acc[2*pr + 1], ahr, bh + 2);
        mma_bf16(acc[2*pr],     ahr, bl);
        mma_bf16(acc[2*pr + 1], ahr, bl + 2);
        mma_bf16(acc[2*pr],     alr, bh);
        mma_bf16(acc[2*pr + 1], alr, bh + 2);
    }

    int gr = lane >> 2, jc = (lane & 3)*2;
    int a1 = saddr[mw*16 + gr];
    int a2 = saddr[mw*16 + gr + 8];
    #pragma unroll
    for (int nt = 0; nt < 8; nt++) {
        int j0 = q*64 + nt*8 + jc;
        if (j0 < 196) {
            float b0 = bs_s[j0];
            if (a1 >= 0) g_w[j0*PLANE + a1] = acc[nt][0] + b0;
            if (a2 >= 0) g_w[j0*PLANE + a2] = acc[nt][2] + b0;
        }
        if (j0 + 1 < 196) {
            float b1 = bs_s[j0 + 1];
            if (a1 >= 0) g_w[(j0+1)*PLANE + a1] = acc[nt][1] + b1;
            if (a2 >= 0) g_w[(j0+1)*PLANE + a2] = acc[nt][3] + b1;
        }
    }
}

// ---------------------------------------------------------------------------
// agg (R13 best config): 256 threads, 32x16 tile, 8 ch/block, grid (4,8,8).
// ---------------------------------------------------------------------------
#define AGG_ROWS 22
#define AGG_PCH  40
#define AGG_CHUNKS (AGG_ROWS*2*AGG_PCH)

__global__ __launch_bounds__(256) void k_agg(const float* __restrict__ src,
                                             float* __restrict__ dst)
{
    __shared__ alignas(16) float xs[AGG_CHUNKS*4];

    int g    = blockIdx.z >> 1;
    int half = blockIdx.z & 1;
    int x0 = blockIdx.x * 32, y0 = blockIdx.y * 16;
    int tid = threadIdx.x;

    for (int i = tid; i < 8*22*38; i += 256) {
        int c = i / 836; int rem = i - c*836;
        int r = rem / 38; int pp = rem - r*38;
        int gy = y0 + r - 3, gx = x0 + pp - 3;
        float v = 0.f;
        if ((unsigned)gy < 126u && (unsigned)gx < 126u)
            v = src[(g*16 + half*8 + c)*PLANE + gy*WP + gx];
        int chunk = (r*2 + (c >> 2))*AGG_PCH + pp;
        int byte = chunk * 16;
        *(float*)((char*)xs + SWZ(byte) + (c & 3)*4) = v;
    }
    __syncthreads();

    int ty = tid >> 4;
    int xp = (tid & 15) * 2;
    int gy = y0 + ty;
    if (gy >= 126) return;
    int gx0 = x0 + xp;

    const float* wbase = g_w + (g*49)*PLANE + gy*WP + gx0;

    float acc[8][2];
    #pragma unroll
    for (int cc = 0; cc < 8; cc++) { acc[cc][0] = 0.f; acc[cc][1] = 0.f; }

    #pragma unroll 1
    for (int kh = 0; kh < 7; kh++) {
        float2 wv[7];
        #pragma unroll
        for (int kw = 0; kw < 7; kw++)
            wv[kw] = *(const float2*)(wbase + (kh*7 + kw)*PLANE);

        #pragma unroll
        for (int cg = 0; cg < 2; cg++) {
            int rowbase = ((ty + kh)*2 + cg)*AGG_PCH;
            float4 xq[8];
            #pragma unroll
            for (int j = 0; j < 8; j++) {
                int byte = (rowbase + xp + j) * 16;
                xq[j] = *(const float4*)((const char*)xs + SWZ(byte));
            }
            #pragma unroll
            for (int kw = 0; kw < 7; kw++) {
                #pragma unroll
                for (int q = 0; q < 2; q++) {
                    float w = q ? wv[kw].y : wv[kw].x;
                    float4 xv = xq[q + kw];
                    acc[cg*4+0][q] += w * xv.x;
                    acc[cg*4+1][q] += w * xv.y;
                    acc[cg*4+2][q] += w * xv.z;
                    acc[cg*4+3][q] += w * xv.w;
                }
            }
        }
    }

    #pragma unroll
    for (int cc = 0; cc < 8; cc++) {
        int ch = g*16 + half*8 + cc;
        float* o = dst + ch*PLANE + gy*WP + gx0;
        #pragma unroll
        for (int q = 0; q < 2; q++)
            if (gx0 + q < 126) o[q] = fmaxf(acc[cc][q], 0.f);
    }
}

// ---------------------------------------------------------------------------
// wprep: conv_out weights -> hi/lo bf16 SW128 images
// ---------------------------------------------------------------------------
__global__ __launch_bounds__(256) void k_wprep(const float* __restrict__ cow)
{
    int idx = blockIdx.x * 256 + threadIdx.x;     // 73728
    if (idx >= 73728) return;
    int ic = idx & 63;
    int oc = (idx >> 6) & 127;
    int s  = idx >> 13;
    int kh = s / 3, kw = s - kh*3;
    float w = cow[oc*576 + ic*9 + kh*3 + kw];
    __nv_bfloat16 h = __float2bfloat16(w);
    __nv_bfloat16 l = __float2bfloat16(w - __bfloat162float(h));
    int off = SWZ(oc*128 + ic*2) >> 1;
    g_wth[s*8192 + off] = h;
    g_wtl[s*8192 + off] = l;
}

// ---------------------------------------------------------------------------
// conv_out_mma (R13 proven)
// ---------------------------------------------------------------------------
#define CO_SMEM 90112

__global__ __launch_bounds__(256) void k_conv_out_mma(const float* __restrict__ src,
    const float* __restrict__ bias, float* __restrict__ out)
{
    extern __shared__ char dsm[];
    uint32_t base = smem_u32(dsm);
    uint32_t Th = (base + 1023) & ~1023u;
    uint32_t Tl = Th + 27648;
    uint32_t Wh = Tl + 27648;
    uint32_t Wl = Wh + 16384;
    char* Th_p = dsm + (Th - base);
    char* Tl_p = dsm + (Tl - base);
    char* Wh_p = dsm + (Wh - base);
    char* Wl_p = dsm + (Wl - base);

    int tid = threadIdx.x;
    int lane = tid & 31, w = tid >> 5;
    int y  = blockIdx.x;
    int x0 = blockIdx.y * 64;
    int pxb = (w & 3) * 16;
    int ocb = (w >> 2) * 64;

    for (int i = tid; i < 3*32*66; i += 256) {
        int col = i % 66;
        int rest = i / 66;
        int icp = rest & 31;
        int v = rest >> 5;
        int gcol = x0 + col;
        float f0 = 0.f, f1 = 0.f;
        if (gcol < WP) {
            const float* pp = src + (2*icp)*PLANE + (y+v)*WP + gcol;
            f0 = __ldg(pp);
            f1 = __ldg(pp + PLANE);
        }
        __nv_bfloat16 h0 = __float2bfloat16(f0);
        __nv_bfloat16 h1 = __float2bfloat16(f1);
        __nv_bfloat16 l0 = __float2bfloat16(f0 - __bfloat162float(h0));
        __nv_bfloat16 l1 = __float2bfloat16(f1 - __bfloat162float(h1));
        uint32_t hu = (uint32_t)__bfloat16_as_ushort(h0)
                    | ((uint32_t)__bfloat16_as_ushort(h1) << 16);
        uint32_t lu = (uint32_t)__bfloat16_as_ushort(l0)
                    | ((uint32_t)__bfloat16_as_ushort(l1) << 16);
        uint32_t off = SWZ((uint32_t)((v*72 + col)*128 + icp*4));
        *(uint32_t*)(Th_p + off) = hu;
        *(uint32_t*)(Tl_p + off) = lu;
    }

    int aRow  = lane & 15;
    int aHalf = (lane >> 4) * 8;
    int bRow  = (lane & 7) + ((lane >> 4) << 3);
    int bHalf = ((lane >> 3) & 1) * 8;

    float acc[8][4];
    #pragma unroll
    for (int j = 0; j < 8; j++)
        #pragma unroll
        for (int q = 0; q < 4; q++) acc[j][q] = 0.f;

    #pragma unroll 1
    for (int s = 0; s < 9; s++) {
        int kh = s / 3, kw = s - kh*3;
        __syncthreads();
        {
            const uint4* sh = (const uint4*)(g_wth + s*8192);
            const uint4* sl = (const uint4*)(g_wtl + s*8192);
            uint4* dh = (uint4*)Wh_p;
            uint4* dl = (uint4*)Wl_p;
            #pragma unroll
            for (int i = 0; i < 4; i++) {
                dh[tid + i*256] = __ldg(&sh[tid + i*256]);
                dl[tid + i*256] = __ldg(&sl[tid + i*256]);
            }
        }
        __syncthreads();

        int cA = pxb + aRow + kw;
        uint32_t arow = (uint32_t)((kh*72 + cA)*128);

        #pragma unroll 1
        for (int pass = 0; pass < 3; pass++) {
            uint32_t Ab = (pass == 2) ? Tl : Th;
            uint32_t Bb = (pass == 1) ? Wl : Wh;
            #pragma unroll
            for (int kk = 0; kk < 4; kk++) {
                uint32_t a[4];
                ldm_x4(a, Ab + SWZ(arow + (uint32_t)((kk*16 + aHalf)*2)));
                #pragma unroll
                for (int j = 0; j < 4; j++) {
                    uint32_t b[4];
                    uint32_t boff = (uint32_t)((ocb + j*16 + bRow)*128
                                              + (kk*16 + bHalf)*2);
                    ldm_x4(b, Bb + SWZ(boff));
                    mma_bf16(acc[2*j],     a, b);
                    mma_bf16(acc[2*j + 1], a, b + 2);
                }
            }
        }
    }

    int r0 = lane >> 2;
    int nc = (lane & 3) * 2;
    int x1 = x0 + pxb + r0;
    int x2 = x1 + 8;
    #pragma unroll
    for (int j = 0; j < 8; j++) {
        int oc = ocb + j*8 + nc;
        float b0 = __ldg(bias + oc), b1 = __ldg(bias + oc + 1);
        if (x1 < 124) {
            out[(oc*124 + y)*124 + x1]       = acc[j][0] + b0;
            out[((oc+1)*124 + y)*124 + x1]   = acc[j][1] + b1;
        }
        if (x2 < 124) {
            out[(oc*124 + y)*124 + x2]       = acc[j][2] + b0;
            out[((oc+1)*124 + y)*124 + x2]   = acc[j][3] + b1;
        }
    }
}

// ---------------------------------------------------------------------------
extern "C" void kernel_launch(void* const* d_in, const int* in_sizes, int n_in,
                              void* d_out, int out_size)
{
    const float* input = (const float*)d_in[0];
    const float* ciw   = (const float*)d_in[1];
    const float* cib   = (const float*)d_in[2];
    const float* wr    = (const float*)d_in[3];
    const float* brr   = (const float*)d_in[4];
    const float* gmm   = (const float*)d_in[5];
    const float* bet   = (const float*)d_in[6];
    const float* mu    = (const float*)d_in[7];
    const float* var   = (const float*)d_in[8];
    const float* ws    = (const float*)d_in[9];
    const float* bs    = (const float*)d_in[10];
    const float* cow   = (const float*)d_in[11];
    const float* cob   = (const float*)d_in[12];

    float *px, *py;
    __nv_bfloat16 *ksh, *ksl, *krh, *krl;
    cudaGetSymbolAddress((void**)&px, g_x);
    cudaGetSymbolAddress((void**)&py, g_y);
    cudaGetSymbolAddress((void**)&ksh, g_ksh);
    cudaGetSymbolAddress((void**)&ksl, g_ksl);
    cudaGetSymbolAddress((void**)&krh, g_krh);
    cudaGetSymbolAddress((void**)&krl, g_krl);
    cudaFuncSetAttribute(k_conv_out_mma,
                         cudaFuncAttributeMaxDynamicSharedMemorySize, CO_SMEM);

    k_wprep<<<288, 256>>>(cow);
    k_wprep2<<<96, 256>>>(ws);
    k_wprep3<<<24, 256>>>(wr);
    k_conv_in<<<dim3(63, 64), 256>>>(input, ciw, cib, px);

    float* cur = px;
    float* nxt = py;
    for (int l = 0; l < NLAYER; l++) {
        k_kgen<<<497, 256>>>(cur, krh + l*1024, krl + l*1024,
                             brr + l*16, gmm + l*16, bet + l*16,
                             mu + l*16, var + l*16,
                             ksh + l*4096, ksl + l*4096, bs + l*196);
        k_agg<<<dim3(4, 8, 8), 256>>>(cur, nxt);
        float* t = cur; cur = nxt; nxt = t;
    }
    k_conv_out_mma<<<dim3(124, 2), 256, CO_SMEM>>>(cur, cob, (float*)d_out);
}